// round 12
// baseline (speedup 1.0000x reference)
#include <cuda_runtime.h>
#include <cuda_fp16.h>

#define MAX_NODES 100000

typedef unsigned long long u64;

// fp16 scratch tables: a_n = dw1[0:32]^T z_loop[n] + db1,  b_n = dw1[32:64]^T z_loop[n]
// row = 64 halves = 128 bytes = exactly one cache line.
__device__ __half g_ah[MAX_NODES * 64];
__device__ __half g_bh[MAX_NODES * 64];

// ---- packed f32x2 helpers (sm_103a) ----
__device__ __forceinline__ u64 pack2(float lo, float hi) {
    u64 r; asm("mov.b64 %0, {%1, %2};" : "=l"(r) : "f"(lo), "f"(hi)); return r;
}
__device__ __forceinline__ float2 unpack2(u64 v) {
    float2 f; asm("mov.b64 {%0, %1}, %2;" : "=f"(f.x), "=f"(f.y) : "l"(v)); return f;
}
__device__ __forceinline__ u64 fma2(u64 a, u64 b, u64 c) {
    u64 d; asm("fma.rn.f32x2 %0, %1, %2, %3;" : "=l"(d) : "l"(a), "l"(b), "l"(c)); return d;
}

__device__ __forceinline__ void store_half8(__half* p, const float* v)
{
    __align__(16) __half2 h[4];
    h[0] = __floats2half2_rn(v[0], v[1]);
    h[1] = __floats2half2_rn(v[2], v[3]);
    h[2] = __floats2half2_rn(v[4], v[5]);
    h[3] = __floats2half2_rn(v[6], v[7]);
    *reinterpret_cast<uint4*>(p) = *reinterpret_cast<const uint4*>(h);
}

// ---------------------------------------------------------------------------
// Node kernel: f32x2 FMA, 2 nodes/thread, (128,2) — R8 base, PLUS dual
// accumulator chains in every dot product (depth 16 -> 8) to attack the
// exposed FFMA2 latency at low occupancy.
// ---------------------------------------------------------------------------
__global__ void __launch_bounds__(128, 2)
node_kernel(const float* __restrict__ z_mod,
            const float* __restrict__ w1,   // [32,64]
            const float* __restrict__ b1,   // [64]
            const float* __restrict__ w2,   // [64,32]
            const float* __restrict__ b2,   // [32]
            const float* __restrict__ dw1,  // [64,64]
            const float* __restrict__ db1,  // [64]
            int n_nodes)
{
    __shared__ float s_w1t[64 * 32];   // s_w1t[k*32+c] = w1[c][k]
    __shared__ float s_w2[64 * 32];    // s_w2[k*32+d]  = w2[k][d]
    __shared__ float s_dw1t[64 * 64];  // s_dw1t[k*64+d] = dw1[d][k]
    __shared__ float s_b1[64], s_db1[64], s_b2[32];

    const int t = threadIdx.x;
    for (int idx = t; idx < 64 * 32; idx += 128) {
        int k = idx >> 5, c = idx & 31;
        s_w1t[idx] = w1[c * 64 + k];
        s_w2[idx]  = w2[idx];
    }
    for (int idx = t; idx < 64 * 64; idx += 128) {
        int k = idx >> 6, d = idx & 63;
        s_dw1t[idx] = dw1[d * 64 + k];
    }
    if (t < 64) { s_b1[t] = b1[t]; s_db1[t] = db1[t]; }
    if (t < 32) { s_b2[t] = b2[t]; }
    __syncthreads();

    int n0 = blockIdx.x * 256 + t;
    if (n0 >= n_nodes) return;
    int n1 = n0 + 128;
    if (n1 >= n_nodes) n1 = n_nodes - 1;  // duplicate compute; identical store race benign

    u64 z0[16], z1[16];
    {
        const ulonglong2* zp0 = reinterpret_cast<const ulonglong2*>(z_mod + (size_t)n0 * 32);
        const ulonglong2* zp1 = reinterpret_cast<const ulonglong2*>(z_mod + (size_t)n1 * 32);
#pragma unroll
        for (int c = 0; c < 8; c++) {
            ulonglong2 v0 = zp0[c], v1 = zp1[c];
            z0[2*c] = v0.x; z0[2*c+1] = v0.y;
            z1[2*c] = v1.x; z1[2*c+1] = v1.y;
        }
    }

    u64 zl0[16], zl1[16];
#pragma unroll
    for (int p = 0; p < 16; p++) {
        u64 bp = pack2(s_b2[2*p], s_b2[2*p+1]);
        zl0[p] = bp; zl1[p] = bp;
    }

#pragma unroll 4
    for (int k = 0; k < 64; k++) {
        // dual chains: even packs -> *a, odd packs -> *b (depth 8 each)
        u64 acc0a = pack2(s_b1[k], 0.0f), acc0b = 0ULL;
        u64 acc1a = acc0a,                acc1b = 0ULL;
        const ulonglong2* wr = reinterpret_cast<const ulonglong2*>(&s_w1t[k * 32]);
#pragma unroll
        for (int c = 0; c < 8; c++) {
            ulonglong2 w = wr[c];
            acc0a = fma2(z0[2*c],   w.x, acc0a);
            acc0b = fma2(z0[2*c+1], w.y, acc0b);
            acc1a = fma2(z1[2*c],   w.x, acc1a);
            acc1b = fma2(z1[2*c+1], w.y, acc1b);
        }
        float2 f0a = unpack2(acc0a), f0b = unpack2(acc0b);
        float2 f1a = unpack2(acc1a), f1b = unpack2(acc1b);
        float h0 = fmaxf((f0a.x + f0a.y) + (f0b.x + f0b.y), 0.0f);
        float h1 = fmaxf((f1a.x + f1a.y) + (f1b.x + f1b.y), 0.0f);
        u64 hb0 = pack2(h0, h0);
        u64 hb1 = pack2(h1, h1);
        const ulonglong2* w2r = reinterpret_cast<const ulonglong2*>(&s_w2[k * 32]);
#pragma unroll
        for (int p = 0; p < 8; p++) {
            ulonglong2 w = w2r[p];
            zl0[2*p]   = fma2(hb0, w.x, zl0[2*p]);
            zl0[2*p+1] = fma2(hb0, w.y, zl0[2*p+1]);
            zl1[2*p]   = fma2(hb1, w.x, zl1[2*p]);
            zl1[2*p+1] = fma2(hb1, w.y, zl1[2*p+1]);
        }
    }

    __half* a0p = g_ah + (size_t)n0 * 64;
    __half* b0p = g_bh + (size_t)n0 * 64;
    __half* a1p = g_ah + (size_t)n1 * 64;
    __half* b1p = g_bh + (size_t)n1 * 64;

#pragma unroll 2
    for (int k8 = 0; k8 < 8; k8++) {
        float a0v[8], b0v[8], a1v[8], b1v[8];
#pragma unroll
        for (int q = 0; q < 8; q++) {
            const int k = k8 * 8 + q;
            // dual chains per output (depth 8)
            u64 A0a = pack2(s_db1[k], 0.0f), A0b = 0ULL;
            u64 A1a = A0a,                   A1b = 0ULL;
            u64 B0a = 0ULL, B0b = 0ULL, B1a = 0ULL, B1b = 0ULL;
            const ulonglong2* wr = reinterpret_cast<const ulonglong2*>(&s_dw1t[k * 64]);
#pragma unroll
            for (int p = 0; p < 8; p++) {
                ulonglong2 w = wr[p];
                A0a = fma2(zl0[2*p],   w.x, A0a);
                A0b = fma2(zl0[2*p+1], w.y, A0b);
                A1a = fma2(zl1[2*p],   w.x, A1a);
                A1b = fma2(zl1[2*p+1], w.y, A1b);
            }
#pragma unroll
            for (int p = 0; p < 8; p++) {
                ulonglong2 w = wr[8 + p];
                B0a = fma2(zl0[2*p],   w.x, B0a);
                B0b = fma2(zl0[2*p+1], w.y, B0b);
                B1a = fma2(zl1[2*p],   w.x, B1a);
                B1b = fma2(zl1[2*p+1], w.y, B1b);
            }
            float2 fa0a = unpack2(A0a), fa0b = unpack2(A0b);
            float2 fb0a = unpack2(B0a), fb0b = unpack2(B0b);
            float2 fa1a = unpack2(A1a), fa1b = unpack2(A1b);
            float2 fb1a = unpack2(B1a), fb1b = unpack2(B1b);
            a0v[q] = (fa0a.x + fa0a.y) + (fa0b.x + fa0b.y);
            b0v[q] = (fb0a.x + fb0a.y) + (fb0b.x + fb0b.y);
            a1v[q] = (fa1a.x + fa1a.y) + (fa1b.x + fa1b.y);
            b1v[q] = (fb1a.x + fb1a.y) + (fb1b.x + fb1b.y);
        }
        store_half8(a0p + k8 * 8, a0v);
        store_half8(b0p + k8 * 8, b0v);
        store_half8(a1p + k8 * 8, a1v);
        store_half8(b1p + k8 * 8, b1v);
    }
}

// ---------------------------------------------------------------------------
// Edge kernel (R6 configuration — 67.3us, proven stable across rounds).
// 8 lanes/edge, subgroup owns 4 consecutive edges: int4 idx loads,
// 8 front-batched gathers, zero hot-path predication, one STG.128.
// ---------------------------------------------------------------------------
__device__ __forceinline__ float edge_dot(uint4 ua, uint4 ub,
                                          float4 w0, float4 w1)
{
    const __half2* pa = reinterpret_cast<const __half2*>(&ua);
    const __half2* pb = reinterpret_cast<const __half2*>(&ub);
    const __half2 zero2 = __float2half2_rn(0.0f);
    float2 f0 = __half22float2(__hmax2(__hadd2(pa[0], pb[0]), zero2));
    float2 f1 = __half22float2(__hmax2(__hadd2(pa[1], pb[1]), zero2));
    float2 f2 = __half22float2(__hmax2(__hadd2(pa[2], pb[2]), zero2));
    float2 f3 = __half22float2(__hmax2(__hadd2(pa[3], pb[3]), zero2));
    float acc;
    acc = f0.x * w0.x;
    acc = fmaf(f0.y, w0.y, acc);
    acc = fmaf(f1.x, w0.z, acc);
    acc = fmaf(f1.y, w0.w, acc);
    acc = fmaf(f2.x, w1.x, acc);
    acc = fmaf(f2.y, w1.y, acc);
    acc = fmaf(f3.x, w1.z, acc);
    acc = fmaf(f3.y, w1.w, acc);
    return acc;
}

__global__ void __launch_bounds__(256)
edge_kernel(const int* __restrict__ edge_index,  // [2, E] int32
            const float* __restrict__ dw2,       // [64]
            const float* __restrict__ db2,       // [1]
            float* __restrict__ out, int n_edges)
{
    const int lane = threadIdx.x & 31;
    const int s    = lane >> 3;   // subgroup 0..3
    const int q    = lane & 7;    // lane within subgroup
    const int warp_g = (blockIdx.x * blockDim.x + threadIdx.x) >> 5;
    const int e0 = warp_g * 16 + s * 4;   // 4 consecutive edges per subgroup

    const float4 w0 = __ldg(reinterpret_cast<const float4*>(dw2) + 2 * q);
    const float4 w1 = __ldg(reinterpret_cast<const float4*>(dw2) + 2 * q + 1);
    const float bias = __ldg(db2);
    const uint4* Ab = reinterpret_cast<const uint4*>(g_ah);
    const uint4* Bb = reinterpret_cast<const uint4*>(g_bh);
    const unsigned mask = 0xFFu << (s * 8);

    if (e0 + 4 <= n_edges && (n_edges & 3) == 0) {
        // ---- fast path: no predication ----
        const int4 iv = __ldg(reinterpret_cast<const int4*>(edge_index + e0));
        const int4 jv = __ldg(reinterpret_cast<const int4*>(edge_index + n_edges + e0));

        const uint4 ua0 = Ab[(size_t)iv.x * 8 + q];
        const uint4 ub0 = Bb[(size_t)jv.x * 8 + q];
        const uint4 ua1 = Ab[(size_t)iv.y * 8 + q];
        const uint4 ub1 = Bb[(size_t)jv.y * 8 + q];
        const uint4 ua2 = Ab[(size_t)iv.z * 8 + q];
        const uint4 ub2 = Bb[(size_t)jv.z * 8 + q];
        const uint4 ua3 = Ab[(size_t)iv.w * 8 + q];
        const uint4 ub3 = Bb[(size_t)jv.w * 8 + q];

        float r0 = edge_dot(ua0, ub0, w0, w1);
        float r1 = edge_dot(ua1, ub1, w0, w1);
        float r2 = edge_dot(ua2, ub2, w0, w1);
        float r3 = edge_dot(ua3, ub3, w0, w1);

        r0 += __shfl_xor_sync(mask, r0, 4);
        r1 += __shfl_xor_sync(mask, r1, 4);
        r2 += __shfl_xor_sync(mask, r2, 4);
        r3 += __shfl_xor_sync(mask, r3, 4);
        r0 += __shfl_xor_sync(mask, r0, 2);
        r1 += __shfl_xor_sync(mask, r1, 2);
        r2 += __shfl_xor_sync(mask, r2, 2);
        r3 += __shfl_xor_sync(mask, r3, 2);
        r0 += __shfl_xor_sync(mask, r0, 1);
        r1 += __shfl_xor_sync(mask, r1, 1);
        r2 += __shfl_xor_sync(mask, r2, 1);
        r3 += __shfl_xor_sync(mask, r3, 1);

        if (q == 0) {
            *reinterpret_cast<float4*>(out + e0) =
                make_float4(r0 + bias, r1 + bias, r2 + bias, r3 + bias);
        }
    } else {
        // ---- tail / unaligned fallback ----
#pragma unroll
        for (int t = 0; t < 4; t++) {
            const int e = e0 + t;
            const bool live = (e < n_edges);
            int i = 0, j = 0;
            if (live) {
                i = __ldg(edge_index + e);
                j = __ldg(edge_index + n_edges + e);
            }
            uint4 ua = make_uint4(0, 0, 0, 0), ub = make_uint4(0, 0, 0, 0);
            if (live) {
                ua = Ab[(size_t)i * 8 + q];
                ub = Bb[(size_t)j * 8 + q];
            }
            float acc = edge_dot(ua, ub, w0, w1);
            acc += __shfl_xor_sync(mask, acc, 4);
            acc += __shfl_xor_sync(mask, acc, 2);
            acc += __shfl_xor_sync(mask, acc, 1);
            if (live && q == 0) out[e] = acc + bias;
        }
    }
}

// ---------------------------------------------------------------------------
// Launch. Input order (metadata): z_mod, edge_index, w1, b1, w2, b2,
//                                 dw1, db1, dw2, db2
// ---------------------------------------------------------------------------
extern "C" void kernel_launch(void* const* d_in, const int* in_sizes, int n_in,
                              void* d_out, int out_size)
{
    const float* z_mod = (const float*)d_in[0];
    const int*   eidx  = (const int*)d_in[1];
    const float* w1    = (const float*)d_in[2];
    const float* b1    = (const float*)d_in[3];
    const float* w2    = (const float*)d_in[4];
    const float* b2    = (const float*)d_in[5];
    const float* dw1   = (const float*)d_in[6];
    const float* db1   = (const float*)d_in[7];
    const float* dw2   = (const float*)d_in[8];
    const float* db2   = (const float*)d_in[9];
    float* out = (float*)d_out;

    const int n_nodes = in_sizes[0] / 32;
    const int n_edges = in_sizes[1] / 2;

    const int nb_node = (n_nodes + 255) / 256;   // 128 threads, 2 nodes/thread
    node_kernel<<<nb_node, 128>>>(z_mod, w1, b1, w2, b2, dw1, db1, n_nodes);

    const int nb_edge = (n_edges + 127) / 128;   // 16 edges per warp
    edge_kernel<<<nb_edge, 256>>>(eidx, dw2, db2, out, n_edges);
}

// round 14
// speedup vs baseline: 1.1040x; 1.1040x over previous
#include <cuda_runtime.h>
#include <cuda_fp16.h>
#include <cstdint>
#include <cstddef>

#define MAX_NODES 100000

// fp16 scratch tables: a_n = dw1[0:32]^T z_loop[n] + db1,  b_n = dw1[32:64]^T z_loop[n]
// row = 64 halves = 128 bytes = exactly one cache line.
__device__ __half g_ah[MAX_NODES * 64];
__device__ __half g_bh[MAX_NODES * 64];

// ---------------------------------------------------------------------------
// mma.sync m16n8k16 helpers (fp16 inputs, fp32 accum)
// ---------------------------------------------------------------------------
__device__ __forceinline__ void mma16816(float c[4], const uint32_t a[4],
                                         uint32_t b0, uint32_t b1)
{
    asm volatile(
        "mma.sync.aligned.m16n8k16.row.col.f32.f16.f16.f32 "
        "{%0,%1,%2,%3}, {%4,%5,%6,%7}, {%8,%9}, {%0,%1,%2,%3};"
        : "+f"(c[0]), "+f"(c[1]), "+f"(c[2]), "+f"(c[3])
        : "r"(a[0]), "r"(a[1]), "r"(a[2]), "r"(a[3]), "r"(b0), "r"(b1));
}

__device__ __forceinline__ uint32_t f2_to_h2(float x, float y)
{
    __half2 h = __floats2half2_rn(x, y);
    return *reinterpret_cast<uint32_t*>(&h);
}
__device__ __forceinline__ uint32_t f2_to_h2_relu(float x, float y)
{
    __half2 h = __floats2half2_rn(fmaxf(x, 0.0f), fmaxf(y, 0.0f));
    return *reinterpret_cast<uint32_t*>(&h);
}

// ---------------------------------------------------------------------------
// Node kernel via tensor cores: 3 chained GEMMs per 128-node tile, with
// accumulator->A-fragment register reuse (b2b GEMM trick):
//   h  = relu(z @ w1 + b1)    [128x32]@[32x64]
//   zl = h @ w2 + b2          [128x64]@[64x32]
//   a|b = zl @ dw1' (+db1|0)  [128x32]@[32x128]
// Weights fp16, k-contiguous in smem (one LDS.32 per B fragment reg).
// ---------------------------------------------------------------------------
__global__ void __launch_bounds__(128)
node_kernel(const float* __restrict__ z_mod,
            const float* __restrict__ w1,   // [32,64]
            const float* __restrict__ b1,   // [64]
            const float* __restrict__ w2,   // [64,32]
            const float* __restrict__ b2,   // [32]
            const float* __restrict__ dw1,  // [64,64]
            const float* __restrict__ db1,  // [64]
            int n_nodes)
{
    __shared__ __half s_w1t[64 * 32];   // [n][k] = w1[k][n]
    __shared__ __half s_w2t[32 * 64];   // [n][k] = w2[k][n]
    __shared__ __half s_dw1t[64 * 64];  // [n][kk] = dw1[kk][n]
    __shared__ float s_b1[64], s_b2[32], s_db1[64];

    const int t = threadIdx.x;
    for (int i = t; i < 2048; i += 128) {
        int nn = i >> 5, kk = i & 31;
        s_w1t[i] = __float2half(w1[kk * 64 + nn]);
    }
    for (int i = t; i < 2048; i += 128) {
        int nn = i >> 6, kk = i & 63;
        s_w2t[i] = __float2half(w2[kk * 32 + nn]);
    }
    for (int i = t; i < 4096; i += 128) {
        int nn = i >> 6, kk = i & 63;
        s_dw1t[i] = __float2half(dw1[kk * 64 + nn]);
    }
    if (t < 64) { s_b1[t] = b1[t]; s_db1[t] = db1[t]; }
    if (t < 32) { s_b2[t] = b2[t]; }
    __syncthreads();

    const int wid  = t >> 5;
    const int lane = t & 31;
    const int gid  = lane >> 2;   // row group 0..7
    const int tig  = lane & 3;    // thread in group
    const int rbase = blockIdx.x * 128 + wid * 32;
    const int nlast = n_nodes - 1;

    // ---- A1 fragments from z (fp32 gmem -> fp16) ----
    // A1[mt][ks]: a0=(r,2tig) a1=(r+8,2tig) a2=(r,8+2tig) a3=(r+8,8+2tig)
    uint32_t A1[2][2][4];
#pragma unroll
    for (int mt = 0; mt < 2; mt++) {
        int r0 = rbase + mt * 16 + gid;      if (r0 > nlast) r0 = nlast;
        int r1 = rbase + mt * 16 + gid + 8;  if (r1 > nlast) r1 = nlast;
#pragma unroll
        for (int ks = 0; ks < 2; ks++) {
            const float2* p0 = reinterpret_cast<const float2*>(z_mod + (size_t)r0 * 32 + ks * 16);
            const float2* p1 = reinterpret_cast<const float2*>(z_mod + (size_t)r1 * 32 + ks * 16);
            float2 v;
            v = p0[tig];     A1[mt][ks][0] = f2_to_h2(v.x, v.y);
            v = p1[tig];     A1[mt][ks][1] = f2_to_h2(v.x, v.y);
            v = p0[tig + 4]; A1[mt][ks][2] = f2_to_h2(v.x, v.y);
            v = p1[tig + 4]; A1[mt][ks][3] = f2_to_h2(v.x, v.y);
        }
    }

    // ---- GEMM1: C1[2][8] = z @ w1 + b1 ----
    float C1[2][8][4];
#pragma unroll
    for (int nt = 0; nt < 8; nt++) {
        float2 bb = *reinterpret_cast<const float2*>(&s_b1[nt * 8 + 2 * tig]);
#pragma unroll
        for (int mt = 0; mt < 2; mt++) {
            C1[mt][nt][0] = bb.x; C1[mt][nt][1] = bb.y;
            C1[mt][nt][2] = bb.x; C1[mt][nt][3] = bb.y;
        }
    }
#pragma unroll
    for (int nt = 0; nt < 8; nt++) {
#pragma unroll
        for (int ks = 0; ks < 2; ks++) {
            const __half* wp = &s_w1t[(nt * 8 + gid) * 32 + ks * 16 + 2 * tig];
            uint32_t b0 = *reinterpret_cast<const uint32_t*>(wp);
            uint32_t b1v = *reinterpret_cast<const uint32_t*>(wp + 8);
            mma16816(C1[0][nt], A1[0][ks], b0, b1v);
            mma16816(C1[1][nt], A1[1][ks], b0, b1v);
        }
    }

    // ---- relu + pack -> A2 (k=64, 4 ktiles) ----
    uint32_t A2[2][4][4];
#pragma unroll
    for (int mt = 0; mt < 2; mt++)
#pragma unroll
        for (int kt = 0; kt < 4; kt++) {
            A2[mt][kt][0] = f2_to_h2_relu(C1[mt][2*kt][0],   C1[mt][2*kt][1]);
            A2[mt][kt][1] = f2_to_h2_relu(C1[mt][2*kt][2],   C1[mt][2*kt][3]);
            A2[mt][kt][2] = f2_to_h2_relu(C1[mt][2*kt+1][0], C1[mt][2*kt+1][1]);
            A2[mt][kt][3] = f2_to_h2_relu(C1[mt][2*kt+1][2], C1[mt][2*kt+1][3]);
        }

    // ---- GEMM2: C2[2][4] = h @ w2 + b2 (no relu after) ----
    float C2[2][4][4];
#pragma unroll
    for (int nt = 0; nt < 4; nt++) {
        float2 bb = *reinterpret_cast<const float2*>(&s_b2[nt * 8 + 2 * tig]);
#pragma unroll
        for (int mt = 0; mt < 2; mt++) {
            C2[mt][nt][0] = bb.x; C2[mt][nt][1] = bb.y;
            C2[mt][nt][2] = bb.x; C2[mt][nt][3] = bb.y;
        }
    }
#pragma unroll
    for (int nt = 0; nt < 4; nt++) {
#pragma unroll
        for (int ks = 0; ks < 4; ks++) {
            const __half* wp = &s_w2t[(nt * 8 + gid) * 64 + ks * 16 + 2 * tig];
            uint32_t b0 = *reinterpret_cast<const uint32_t*>(wp);
            uint32_t b1v = *reinterpret_cast<const uint32_t*>(wp + 8);
            mma16816(C2[0][nt], A2[0][ks], b0, b1v);
            mma16816(C2[1][nt], A2[1][ks], b0, b1v);
        }
    }

    // ---- pack zl -> A3 (k=32, 2 ktiles; NO relu) ----
    uint32_t A3[2][2][4];
#pragma unroll
    for (int mt = 0; mt < 2; mt++)
#pragma unroll
        for (int kt = 0; kt < 2; kt++) {
            A3[mt][kt][0] = f2_to_h2(C2[mt][2*kt][0],   C2[mt][2*kt][1]);
            A3[mt][kt][1] = f2_to_h2(C2[mt][2*kt][2],   C2[mt][2*kt][3]);
            A3[mt][kt][2] = f2_to_h2(C2[mt][2*kt+1][0], C2[mt][2*kt+1][1]);
            A3[mt][kt][3] = f2_to_h2(C2[mt][2*kt+1][2], C2[mt][2*kt+1][3]);
        }

    // ---- GEMM3 in two halves: h=0 -> a (bias db1, dw1 rows 0:32),
    //                           h=1 -> b (bias 0,  dw1 rows 32:64) ----
#pragma unroll
    for (int hh = 0; hh < 2; hh++) {
        float C3[2][8][4];
#pragma unroll
        for (int nt = 0; nt < 8; nt++) {
            float bx = 0.0f, by = 0.0f;
            if (hh == 0) {
                float2 bb = *reinterpret_cast<const float2*>(&s_db1[nt * 8 + 2 * tig]);
                bx = bb.x; by = bb.y;
            }
#pragma unroll
            for (int mt = 0; mt < 2; mt++) {
                C3[mt][nt][0] = bx; C3[mt][nt][1] = by;
                C3[mt][nt][2] = bx; C3[mt][nt][3] = by;
            }
        }
        const int koff = hh * 32;
#pragma unroll
        for (int nt = 0; nt < 8; nt++) {
#pragma unroll
            for (int ks = 0; ks < 2; ks++) {
                const __half* wp = &s_dw1t[(nt * 8 + gid) * 64 + koff + ks * 16 + 2 * tig];
                uint32_t b0 = *reinterpret_cast<const uint32_t*>(wp);
                uint32_t b1v = *reinterpret_cast<const uint32_t*>(wp + 8);
                mma16816(C3[0][nt], A3[0][ks], b0, b1v);
                mma16816(C3[1][nt], A3[1][ks], b0, b1v);
            }
        }
        __half* dst = hh ? g_bh : g_ah;
#pragma unroll
        for (int mt = 0; mt < 2; mt++) {
            const int r0 = rbase + mt * 16 + gid;
            const int r1 = r0 + 8;
#pragma unroll
            for (int nt = 0; nt < 8; nt++) {
                uint32_t p01 = f2_to_h2(C3[mt][nt][0], C3[mt][nt][1]);
                uint32_t p23 = f2_to_h2(C3[mt][nt][2], C3[mt][nt][3]);
                if (r0 < n_nodes)
                    *reinterpret_cast<uint32_t*>(&dst[(size_t)r0 * 64 + nt * 8 + 2 * tig]) = p01;
                if (r1 < n_nodes)
                    *reinterpret_cast<uint32_t*>(&dst[(size_t)r1 * 64 + nt * 8 + 2 * tig]) = p23;
            }
        }
    }
}

// ---------------------------------------------------------------------------
// Edge kernel (R6 configuration — 67.3us, proven stable).
// 8 lanes/edge, subgroup owns 4 consecutive edges: int4 idx loads,
// 8 front-batched gathers, zero hot-path predication, one STG.128.
// ---------------------------------------------------------------------------
__device__ __forceinline__ float edge_dot(uint4 ua, uint4 ub,
                                          float4 w0, float4 w1)
{
    const __half2* pa = reinterpret_cast<const __half2*>(&ua);
    const __half2* pb = reinterpret_cast<const __half2*>(&ub);
    const __half2 zero2 = __float2half2_rn(0.0f);
    float2 f0 = __half22float2(__hmax2(__hadd2(pa[0], pb[0]), zero2));
    float2 f1 = __half22float2(__hmax2(__hadd2(pa[1], pb[1]), zero2));
    float2 f2 = __half22float2(__hmax2(__hadd2(pa[2], pb[2]), zero2));
    float2 f3 = __half22float2(__hmax2(__hadd2(pa[3], pb[3]), zero2));
    float acc;
    acc = f0.x * w0.x;
    acc = fmaf(f0.y, w0.y, acc);
    acc = fmaf(f1.x, w0.z, acc);
    acc = fmaf(f1.y, w0.w, acc);
    acc = fmaf(f2.x, w1.x, acc);
    acc = fmaf(f2.y, w1.y, acc);
    acc = fmaf(f3.x, w1.z, acc);
    acc = fmaf(f3.y, w1.w, acc);
    return acc;
}

__global__ void __launch_bounds__(256)
edge_kernel(const int* __restrict__ edge_index,  // [2, E] int32
            const float* __restrict__ dw2,       // [64]
            const float* __restrict__ db2,       // [1]
            float* __restrict__ out, int n_edges)
{
    const int lane = threadIdx.x & 31;
    const int s    = lane >> 3;   // subgroup 0..3
    const int q    = lane & 7;    // lane within subgroup
    const int warp_g = (blockIdx.x * blockDim.x + threadIdx.x) >> 5;
    const int e0 = warp_g * 16 + s * 4;   // 4 consecutive edges per subgroup

    const float4 w0 = __ldg(reinterpret_cast<const float4*>(dw2) + 2 * q);
    const float4 w1 = __ldg(reinterpret_cast<const float4*>(dw2) + 2 * q + 1);
    const float bias = __ldg(db2);
    const uint4* Ab = reinterpret_cast<const uint4*>(g_ah);
    const uint4* Bb = reinterpret_cast<const uint4*>(g_bh);
    const unsigned mask = 0xFFu << (s * 8);

    if (e0 + 4 <= n_edges && (n_edges & 3) == 0) {
        // ---- fast path: no predication ----
        const int4 iv = __ldg(reinterpret_cast<const int4*>(edge_index + e0));
        const int4 jv = __ldg(reinterpret_cast<const int4*>(edge_index + n_edges + e0));

        const uint4 ua0 = Ab[(size_t)iv.x * 8 + q];
        const uint4 ub0 = Bb[(size_t)jv.x * 8 + q];
        const uint4 ua1 = Ab[(size_t)iv.y * 8 + q];
        const uint4 ub1 = Bb[(size_t)jv.y * 8 + q];
        const uint4 ua2 = Ab[(size_t)iv.z * 8 + q];
        const uint4 ub2 = Bb[(size_t)jv.z * 8 + q];
        const uint4 ua3 = Ab[(size_t)iv.w * 8 + q];
        const uint4 ub3 = Bb[(size_t)jv.w * 8 + q];

        float r0 = edge_dot(ua0, ub0, w0, w1);
        float r1 = edge_dot(ua1, ub1, w0, w1);
        float r2 = edge_dot(ua2, ub2, w0, w1);
        float r3 = edge_dot(ua3, ub3, w0, w1);

        r0 += __shfl_xor_sync(mask, r0, 4);
        r1 += __shfl_xor_sync(mask, r1, 4);
        r2 += __shfl_xor_sync(mask, r2, 4);
        r3 += __shfl_xor_sync(mask, r3, 4);
        r0 += __shfl_xor_sync(mask, r0, 2);
        r1 += __shfl_xor_sync(mask, r1, 2);
        r2 += __shfl_xor_sync(mask, r2, 2);
        r3 += __shfl_xor_sync(mask, r3, 2);
        r0 += __shfl_xor_sync(mask, r0, 1);
        r1 += __shfl_xor_sync(mask, r1, 1);
        r2 += __shfl_xor_sync(mask, r2, 1);
        r3 += __shfl_xor_sync(mask, r3, 1);

        if (q == 0) {
            *reinterpret_cast<float4*>(out + e0) =
                make_float4(r0 + bias, r1 + bias, r2 + bias, r3 + bias);
        }
    } else {
        // ---- tail / unaligned fallback ----
#pragma unroll
        for (int t = 0; t < 4; t++) {
            const int e = e0 + t;
            const bool live = (e < n_edges);
            int i = 0, j = 0;
            if (live) {
                i = __ldg(edge_index + e);
                j = __ldg(edge_index + n_edges + e);
            }
            uint4 ua = make_uint4(0, 0, 0, 0), ub = make_uint4(0, 0, 0, 0);
            if (live) {
                ua = Ab[(size_t)i * 8 + q];
                ub = Bb[(size_t)j * 8 + q];
            }
            float acc = edge_dot(ua, ub, w0, w1);
            acc += __shfl_xor_sync(mask, acc, 4);
            acc += __shfl_xor_sync(mask, acc, 2);
            acc += __shfl_xor_sync(mask, acc, 1);
            if (live && q == 0) out[e] = acc + bias;
        }
    }
}

// ---------------------------------------------------------------------------
// Launch. Input order (metadata): z_mod, edge_index, w1, b1, w2, b2,
//                                 dw1, db1, dw2, db2
// ---------------------------------------------------------------------------
extern "C" void kernel_launch(void* const* d_in, const int* in_sizes, int n_in,
                              void* d_out, int out_size)
{
    const float* z_mod = (const float*)d_in[0];
    const int*   eidx  = (const int*)d_in[1];
    const float* w1    = (const float*)d_in[2];
    const float* b1    = (const float*)d_in[3];
    const float* w2    = (const float*)d_in[4];
    const float* b2    = (const float*)d_in[5];
    const float* dw1   = (const float*)d_in[6];
    const float* db1   = (const float*)d_in[7];
    const float* dw2   = (const float*)d_in[8];
    const float* db2   = (const float*)d_in[9];
    float* out = (float*)d_out;

    const int n_nodes = in_sizes[0] / 32;
    const int n_edges = in_sizes[1] / 2;

    const int nb_node = (n_nodes + 127) / 128;   // 128 nodes per 128-thread block
    node_kernel<<<nb_node, 128>>>(z_mod, w1, b1, w2, b2, dw1, db1, n_nodes);

    const int nb_edge = (n_edges + 127) / 128;   // 16 edges per warp
    edge_kernel<<<nb_edge, 256>>>(eidx, dw2, db2, out, n_edges);
}

// round 15
// speedup vs baseline: 1.2220x; 1.1069x over previous
#include <cuda_runtime.h>
#include <cuda_fp16.h>
#include <cstdint>
#include <cstddef>

#define MAX_NODES 100000

// fp16 scratch tables: a_n = dw1[0:32]^T z_loop[n] + db1,  b_n = dw1[32:64]^T z_loop[n]
__device__ __half g_ah[MAX_NODES * 64];
__device__ __half g_bh[MAX_NODES * 64];

// ---------------------------------------------------------------------------
// mma.sync m16n8k16 (fp16 in, fp32 accum)
// ---------------------------------------------------------------------------
__device__ __forceinline__ void mma16816(float c[4], const uint32_t a[4],
                                         uint32_t b0, uint32_t b1)
{
    asm volatile(
        "mma.sync.aligned.m16n8k16.row.col.f32.f16.f16.f32 "
        "{%0,%1,%2,%3}, {%4,%5,%6,%7}, {%8,%9}, {%0,%1,%2,%3};"
        : "+f"(c[0]), "+f"(c[1]), "+f"(c[2]), "+f"(c[3])
        : "r"(a[0]), "r"(a[1]), "r"(a[2]), "r"(a[3]), "r"(b0), "r"(b1));
}

__device__ __forceinline__ uint32_t f2_to_h2(float x, float y)
{
    __half2 h = __floats2half2_rn(x, y);
    return *reinterpret_cast<uint32_t*>(&h);
}
__device__ __forceinline__ uint32_t f2_to_h2_relu(float x, float y)
{
    __half2 h = __floats2half2_rn(fmaxf(x, 0.0f), fmaxf(y, 0.0f));
    return *reinterpret_cast<uint32_t*>(&h);
}

// ---------------------------------------------------------------------------
// Node kernel (HMMA): 256 nodes / 256-thread block (8 warps x 32 nodes).
// z loads issued BEFORE weight staging (latency overlap); outputs staged in
// smem then written with coalesced STG.128 (store wavefronts / 4).
// ---------------------------------------------------------------------------
__global__ void __launch_bounds__(256)
node_kernel(const float* __restrict__ z_mod,
            const float* __restrict__ w1,   // [32,64]
            const float* __restrict__ b1,   // [64]
            const float* __restrict__ w2,   // [64,32]
            const float* __restrict__ b2,   // [32]
            const float* __restrict__ dw1,  // [64,64]
            const float* __restrict__ db1,  // [64]
            int n_nodes)
{
    __shared__ __half s_w1t[64 * 32];   // [n][k] = w1[k][n]
    __shared__ __half s_w2t[32 * 64];   // [n][k] = w2[k][n]
    __shared__ __half s_dw1t[64 * 64];  // [n][kk] = dw1[kk][n]
    __shared__ float s_b1[64], s_b2[32], s_db1[64];
    __shared__ __half s_out[256 * 64];  // 32KB staging, reused for a then b

    const int t = threadIdx.x;
    const int wid  = t >> 5;
    const int lane = t & 31;
    const int gid  = lane >> 2;   // row group 0..7
    const int tig  = lane & 3;    // thread in group
    const int rbase = blockIdx.x * 256 + wid * 32;
    const int nlast = n_nodes - 1;

    // ---- issue z loads FIRST (hide LDG latency under weight staging) ----
    float2 zraw[2][2][4];
#pragma unroll
    for (int mt = 0; mt < 2; mt++) {
        int r0 = rbase + mt * 16 + gid;      if (r0 > nlast) r0 = nlast;
        int r1 = rbase + mt * 16 + gid + 8;  if (r1 > nlast) r1 = nlast;
#pragma unroll
        for (int ks = 0; ks < 2; ks++) {
            const float2* p0 = reinterpret_cast<const float2*>(z_mod + (size_t)r0 * 32 + ks * 16);
            const float2* p1 = reinterpret_cast<const float2*>(z_mod + (size_t)r1 * 32 + ks * 16);
            zraw[mt][ks][0] = p0[tig];
            zraw[mt][ks][1] = p1[tig];
            zraw[mt][ks][2] = p0[tig + 4];
            zraw[mt][ks][3] = p1[tig + 4];
        }
    }

    // ---- weight staging (fp32 -> fp16, transposed) ----
    for (int i = t; i < 2048; i += 256) {
        int nn = i >> 5, kk = i & 31;
        s_w1t[i] = __float2half(w1[kk * 64 + nn]);
    }
    for (int i = t; i < 2048; i += 256) {
        int nn = i >> 6, kk = i & 63;
        s_w2t[i] = __float2half(w2[kk * 32 + nn]);
    }
    for (int i = t; i < 4096; i += 256) {
        int nn = i >> 6, kk = i & 63;
        s_dw1t[i] = __float2half(dw1[kk * 64 + nn]);
    }
    if (t < 64) { s_b1[t] = b1[t]; s_db1[t] = db1[t]; }
    if (t < 32) { s_b2[t] = b2[t]; }
    __syncthreads();

    // ---- pack A1 fragments ----
    uint32_t A1[2][2][4];
#pragma unroll
    for (int mt = 0; mt < 2; mt++)
#pragma unroll
        for (int ks = 0; ks < 2; ks++)
#pragma unroll
            for (int r = 0; r < 4; r++)
                A1[mt][ks][r] = f2_to_h2(zraw[mt][ks][r].x, zraw[mt][ks][r].y);

    // ---- GEMM1: C1 = z @ w1 + b1 ----
    float C1[2][8][4];
#pragma unroll
    for (int nt = 0; nt < 8; nt++) {
        float2 bb = *reinterpret_cast<const float2*>(&s_b1[nt * 8 + 2 * tig]);
#pragma unroll
        for (int mt = 0; mt < 2; mt++) {
            C1[mt][nt][0] = bb.x; C1[mt][nt][1] = bb.y;
            C1[mt][nt][2] = bb.x; C1[mt][nt][3] = bb.y;
        }
    }
#pragma unroll
    for (int nt = 0; nt < 8; nt++) {
#pragma unroll
        for (int ks = 0; ks < 2; ks++) {
            const __half* wp = &s_w1t[(nt * 8 + gid) * 32 + ks * 16 + 2 * tig];
            uint32_t b0 = *reinterpret_cast<const uint32_t*>(wp);
            uint32_t b1v = *reinterpret_cast<const uint32_t*>(wp + 8);
            mma16816(C1[0][nt], A1[0][ks], b0, b1v);
            mma16816(C1[1][nt], A1[1][ks], b0, b1v);
        }
    }

    // ---- relu + pack -> A2 ----
    uint32_t A2[2][4][4];
#pragma unroll
    for (int mt = 0; mt < 2; mt++)
#pragma unroll
        for (int kt = 0; kt < 4; kt++) {
            A2[mt][kt][0] = f2_to_h2_relu(C1[mt][2*kt][0],   C1[mt][2*kt][1]);
            A2[mt][kt][1] = f2_to_h2_relu(C1[mt][2*kt][2],   C1[mt][2*kt][3]);
            A2[mt][kt][2] = f2_to_h2_relu(C1[mt][2*kt+1][0], C1[mt][2*kt+1][1]);
            A2[mt][kt][3] = f2_to_h2_relu(C1[mt][2*kt+1][2], C1[mt][2*kt+1][3]);
        }

    // ---- GEMM2: C2 = h @ w2 + b2 ----
    float C2[2][4][4];
#pragma unroll
    for (int nt = 0; nt < 4; nt++) {
        float2 bb = *reinterpret_cast<const float2*>(&s_b2[nt * 8 + 2 * tig]);
#pragma unroll
        for (int mt = 0; mt < 2; mt++) {
            C2[mt][nt][0] = bb.x; C2[mt][nt][1] = bb.y;
            C2[mt][nt][2] = bb.x; C2[mt][nt][3] = bb.y;
        }
    }
#pragma unroll
    for (int nt = 0; nt < 4; nt++) {
#pragma unroll
        for (int ks = 0; ks < 4; ks++) {
            const __half* wp = &s_w2t[(nt * 8 + gid) * 64 + ks * 16 + 2 * tig];
            uint32_t b0 = *reinterpret_cast<const uint32_t*>(wp);
            uint32_t b1v = *reinterpret_cast<const uint32_t*>(wp + 8);
            mma16816(C2[0][nt], A2[0][ks], b0, b1v);
            mma16816(C2[1][nt], A2[1][ks], b0, b1v);
        }
    }

    // ---- pack zl -> A3 (no relu) ----
    uint32_t A3[2][2][4];
#pragma unroll
    for (int mt = 0; mt < 2; mt++)
#pragma unroll
        for (int kt = 0; kt < 2; kt++) {
            A3[mt][kt][0] = f2_to_h2(C2[mt][2*kt][0],   C2[mt][2*kt][1]);
            A3[mt][kt][1] = f2_to_h2(C2[mt][2*kt][2],   C2[mt][2*kt][3]);
            A3[mt][kt][2] = f2_to_h2(C2[mt][2*kt+1][0], C2[mt][2*kt+1][1]);
            A3[mt][kt][3] = f2_to_h2(C2[mt][2*kt+1][2], C2[mt][2*kt+1][3]);
        }

    // ---- GEMM3 halves: hh=0 -> a (bias db1), hh=1 -> b (bias 0) ----
#pragma unroll
    for (int hh = 0; hh < 2; hh++) {
        float C3[2][8][4];
#pragma unroll
        for (int nt = 0; nt < 8; nt++) {
            float bx = 0.0f, by = 0.0f;
            if (hh == 0) {
                float2 bb = *reinterpret_cast<const float2*>(&s_db1[nt * 8 + 2 * tig]);
                bx = bb.x; by = bb.y;
            }
#pragma unroll
            for (int mt = 0; mt < 2; mt++) {
                C3[mt][nt][0] = bx; C3[mt][nt][1] = by;
                C3[mt][nt][2] = bx; C3[mt][nt][3] = by;
            }
        }
        const int koff = hh * 32;
#pragma unroll
        for (int nt = 0; nt < 8; nt++) {
#pragma unroll
            for (int ks = 0; ks < 2; ks++) {
                const __half* wp = &s_dw1t[(nt * 8 + gid) * 64 + koff + ks * 16 + 2 * tig];
                uint32_t b0 = *reinterpret_cast<const uint32_t*>(wp);
                uint32_t b1v = *reinterpret_cast<const uint32_t*>(wp + 8);
                mma16816(C3[0][nt], A3[0][ks], b0, b1v);
                mma16816(C3[1][nt], A3[1][ks], b0, b1v);
            }
        }

        // stage to smem (scattered STS is cheap), then coalesced STG.128
        __syncthreads();   // protect buffer reuse between hh passes
#pragma unroll
        for (int mt = 0; mt < 2; mt++) {
            const int lr0 = wid * 32 + mt * 16 + gid;  // local row
            const int lr1 = lr0 + 8;
#pragma unroll
            for (int nt = 0; nt < 8; nt++) {
                *reinterpret_cast<uint32_t*>(&s_out[lr0 * 64 + nt * 8 + 2 * tig]) =
                    f2_to_h2(C3[mt][nt][0], C3[mt][nt][1]);
                *reinterpret_cast<uint32_t*>(&s_out[lr1 * 64 + nt * 8 + 2 * tig]) =
                    f2_to_h2(C3[mt][nt][2], C3[mt][nt][3]);
            }
        }
        __syncthreads();

        __half* dst = hh ? g_bh : g_ah;
        const int blk0 = blockIdx.x * 256;
        // 256 rows x 128B = 2048 uint4; 256 threads -> 8 iters, coalesced
#pragma unroll
        for (int it = 0; it < 8; it++) {
            int idx = it * 256 + t;          // uint4 index
            int row = blk0 + (idx >> 3);
            if (row < n_nodes) {
                reinterpret_cast<uint4*>(dst)[(size_t)row * 8 + (idx & 7)] =
                    reinterpret_cast<const uint4*>(s_out)[idx];
            }
        }
    }
}

// ---------------------------------------------------------------------------
// Edge kernel (R6 configuration — 67.3us, proven stable).
// ---------------------------------------------------------------------------
__device__ __forceinline__ float edge_dot(uint4 ua, uint4 ub,
                                          float4 w0, float4 w1)
{
    const __half2* pa = reinterpret_cast<const __half2*>(&ua);
    const __half2* pb = reinterpret_cast<const __half2*>(&ub);
    const __half2 zero2 = __float2half2_rn(0.0f);
    float2 f0 = __half22float2(__hmax2(__hadd2(pa[0], pb[0]), zero2));
    float2 f1 = __half22float2(__hmax2(__hadd2(pa[1], pb[1]), zero2));
    float2 f2 = __half22float2(__hmax2(__hadd2(pa[2], pb[2]), zero2));
    float2 f3 = __half22float2(__hmax2(__hadd2(pa[3], pb[3]), zero2));
    float acc;
    acc = f0.x * w0.x;
    acc = fmaf(f0.y, w0.y, acc);
    acc = fmaf(f1.x, w0.z, acc);
    acc = fmaf(f1.y, w0.w, acc);
    acc = fmaf(f2.x, w1.x, acc);
    acc = fmaf(f2.y, w1.y, acc);
    acc = fmaf(f3.x, w1.z, acc);
    acc = fmaf(f3.y, w1.w, acc);
    return acc;
}

__global__ void __launch_bounds__(256)
edge_kernel(const int* __restrict__ edge_index,  // [2, E] int32
            const float* __restrict__ dw2,       // [64]
            const float* __restrict__ db2,       // [1]
            float* __restrict__ out, int n_edges)
{
    const int lane = threadIdx.x & 31;
    const int s    = lane >> 3;   // subgroup 0..3
    const int q    = lane & 7;    // lane within subgroup
    const int warp_g = (blockIdx.x * blockDim.x + threadIdx.x) >> 5;
    const int e0 = warp_g * 16 + s * 4;

    const float4 w0 = __ldg(reinterpret_cast<const float4*>(dw2) + 2 * q);
    const float4 w1 = __ldg(reinterpret_cast<const float4*>(dw2) + 2 * q + 1);
    const float bias = __ldg(db2);
    const uint4* Ab = reinterpret_cast<const uint4*>(g_ah);
    const uint4* Bb = reinterpret_cast<const uint4*>(g_bh);
    const unsigned mask = 0xFFu << (s * 8);

    if (e0 + 4 <= n_edges && (n_edges & 3) == 0) {
        const int4 iv = __ldg(reinterpret_cast<const int4*>(edge_index + e0));
        const int4 jv = __ldg(reinterpret_cast<const int4*>(edge_index + n_edges + e0));

        const uint4 ua0 = Ab[(size_t)iv.x * 8 + q];
        const uint4 ub0 = Bb[(size_t)jv.x * 8 + q];
        const uint4 ua1 = Ab[(size_t)iv.y * 8 + q];
        const uint4 ub1 = Bb[(size_t)jv.y * 8 + q];
        const uint4 ua2 = Ab[(size_t)iv.z * 8 + q];
        const uint4 ub2 = Bb[(size_t)jv.z * 8 + q];
        const uint4 ua3 = Ab[(size_t)iv.w * 8 + q];
        const uint4 ub3 = Bb[(size_t)jv.w * 8 + q];

        float r0 = edge_dot(ua0, ub0, w0, w1);
        float r1 = edge_dot(ua1, ub1, w0, w1);
        float r2 = edge_dot(ua2, ub2, w0, w1);
        float r3 = edge_dot(ua3, ub3, w0, w1);

        r0 += __shfl_xor_sync(mask, r0, 4);
        r1 += __shfl_xor_sync(mask, r1, 4);
        r2 += __shfl_xor_sync(mask, r2, 4);
        r3 += __shfl_xor_sync(mask, r3, 4);
        r0 += __shfl_xor_sync(mask, r0, 2);
        r1 += __shfl_xor_sync(mask, r1, 2);
        r2 += __shfl_xor_sync(mask, r2, 2);
        r3 += __shfl_xor_sync(mask, r3, 2);
        r0 += __shfl_xor_sync(mask, r0, 1);
        r1 += __shfl_xor_sync(mask, r1, 1);
        r2 += __shfl_xor_sync(mask, r2, 1);
        r3 += __shfl_xor_sync(mask, r3, 1);

        if (q == 0) {
            *reinterpret_cast<float4*>(out + e0) =
                make_float4(r0 + bias, r1 + bias, r2 + bias, r3 + bias);
        }
    } else {
#pragma unroll
        for (int t = 0; t < 4; t++) {
            const int e = e0 + t;
            const bool live = (e < n_edges);
            int i = 0, j = 0;
            if (live) {
                i = __ldg(edge_index + e);
                j = __ldg(edge_index + n_edges + e);
            }
            uint4 ua = make_uint4(0, 0, 0, 0), ub = make_uint4(0, 0, 0, 0);
            if (live) {
                ua = Ab[(size_t)i * 8 + q];
                ub = Bb[(size_t)j * 8 + q];
            }
            float acc = edge_dot(ua, ub, w0, w1);
            acc += __shfl_xor_sync(mask, acc, 4);
            acc += __shfl_xor_sync(mask, acc, 2);
            acc += __shfl_xor_sync(mask, acc, 1);
            if (live && q == 0) out[e] = acc + bias;
        }
    }
}

// ---------------------------------------------------------------------------
// Launch. Input order (metadata): z_mod, edge_index, w1, b1, w2, b2,
//                                 dw1, db1, dw2, db2
// ---------------------------------------------------------------------------
extern "C" void kernel_launch(void* const* d_in, const int* in_sizes, int n_in,
                              void* d_out, int out_size)
{
    const float* z_mod = (const float*)d_in[0];
    const int*   eidx  = (const int*)d_in[1];
    const float* w1    = (const float*)d_in[2];
    const float* b1    = (const float*)d_in[3];
    const float* w2    = (const float*)d_in[4];
    const float* b2    = (const float*)d_in[5];
    const float* dw1   = (const float*)d_in[6];
    const float* db1   = (const float*)d_in[7];
    const float* dw2   = (const float*)d_in[8];
    const float* db2   = (const float*)d_in[9];
    float* out = (float*)d_out;

    const int n_nodes = in_sizes[0] / 32;
    const int n_edges = in_sizes[1] / 2;

    const int nb_node = (n_nodes + 255) / 256;   // 256 nodes per 256-thread block
    node_kernel<<<nb_node, 256>>>(z_mod, w1, b1, w2, b2, dw1, db1, n_nodes);

    const int nb_edge = (n_edges + 127) / 128;   // 16 edges per warp
    edge_kernel<<<nb_edge, 256>>>(eidx, dw2, db2, out, n_edges);
}

// round 17
// speedup vs baseline: 1.3538x; 1.1078x over previous
#include <cuda_runtime.h>
#include <cuda_fp16.h>
#include <cstdint>
#include <cstddef>

#define MAX_NODES 100000

// fp16 scratch tables: a_n = dw1[0:32]^T z_loop[n] + db1,  b_n = dw1[32:64]^T z_loop[n]
__device__ __half g_ah[MAX_NODES * 64];
__device__ __half g_bh[MAX_NODES * 64];

// pre-transposed fp16 weight image: [0,2048)=w1t [n][k], [2048,4096)=w2t [n][k],
// [4096,8192)=dw1t [n][kk]  — total 8192 halves = 16KB = 1024 uint4
__device__ __align__(16) __half g_wh[8192];

// ---------------------------------------------------------------------------
// prep: build transposed fp16 weights once per launch (~2us)
// ---------------------------------------------------------------------------
__global__ void prep_kernel(const float* __restrict__ w1,
                            const float* __restrict__ w2,
                            const float* __restrict__ dw1)
{
    const int t = blockIdx.x * blockDim.x + threadIdx.x;
    const int nthr = gridDim.x * blockDim.x;
    for (int i = t; i < 2048; i += nthr) {
        int nn = i >> 5, kk = i & 31;
        g_wh[i] = __float2half(w1[kk * 64 + nn]);
    }
    for (int i = t; i < 2048; i += nthr) {
        int nn = i >> 6, kk = i & 63;
        g_wh[2048 + i] = __float2half(w2[kk * 32 + nn]);
    }
    for (int i = t; i < 4096; i += nthr) {
        int nn = i >> 6, kk = i & 63;
        g_wh[4096 + i] = __float2half(dw1[kk * 64 + nn]);
    }
}

// ---------------------------------------------------------------------------
// mma.sync m16n8k16 (fp16 in, fp32 accum)
// ---------------------------------------------------------------------------
__device__ __forceinline__ void mma16816(float c[4], const uint32_t a[4],
                                         uint32_t b0, uint32_t b1)
{
    asm volatile(
        "mma.sync.aligned.m16n8k16.row.col.f32.f16.f16.f32 "
        "{%0,%1,%2,%3}, {%4,%5,%6,%7}, {%8,%9}, {%0,%1,%2,%3};"
        : "+f"(c[0]), "+f"(c[1]), "+f"(c[2]), "+f"(c[3])
        : "r"(a[0]), "r"(a[1]), "r"(a[2]), "r"(a[3]), "r"(b0), "r"(b1));
}

__device__ __forceinline__ uint32_t f2_to_h2(float x, float y)
{
    __half2 h = __floats2half2_rn(x, y);
    return *reinterpret_cast<uint32_t*>(&h);
}
__device__ __forceinline__ uint32_t f2_to_h2_relu(float x, float y)
{
    __half2 h = __floats2half2_rn(fmaxf(x, 0.0f), fmaxf(y, 0.0f));
    return *reinterpret_cast<uint32_t*>(&h);
}

// ---------------------------------------------------------------------------
// Node kernel (HMMA): 256 nodes / 256-thread block. Weights staged from the
// pre-transposed fp16 image with 1024 uint4 copies (4 per thread).
// z loads issued first; outputs staged in smem -> coalesced STG.128.
// ---------------------------------------------------------------------------
__global__ void __launch_bounds__(256)
node_kernel(const float* __restrict__ z_mod,
            const float* __restrict__ b1,   // [64]
            const float* __restrict__ b2,   // [32]
            const float* __restrict__ db1,  // [64]
            int n_nodes)
{
    __shared__ __half s_wh[8192];       // w1t | w2t | dw1t (16KB)
    __shared__ float s_b1[64], s_b2[32], s_db1[64];
    __shared__ __half s_out[256 * 64];  // 32KB staging, reused a then b

    const int t = threadIdx.x;
    const int wid  = t >> 5;
    const int lane = t & 31;
    const int gid  = lane >> 2;
    const int tig  = lane & 3;
    const int rbase = blockIdx.x * 256 + wid * 32;
    const int nlast = n_nodes - 1;

    // ---- z loads first (hide latency under staging) ----
    float2 zraw[2][2][4];
#pragma unroll
    for (int mt = 0; mt < 2; mt++) {
        int r0 = rbase + mt * 16 + gid;      if (r0 > nlast) r0 = nlast;
        int r1 = rbase + mt * 16 + gid + 8;  if (r1 > nlast) r1 = nlast;
#pragma unroll
        for (int ks = 0; ks < 2; ks++) {
            const float2* p0 = reinterpret_cast<const float2*>(z_mod + (size_t)r0 * 32 + ks * 16);
            const float2* p1 = reinterpret_cast<const float2*>(z_mod + (size_t)r1 * 32 + ks * 16);
            zraw[mt][ks][0] = p0[tig];
            zraw[mt][ks][1] = p1[tig];
            zraw[mt][ks][2] = p0[tig + 4];
            zraw[mt][ks][3] = p1[tig + 4];
        }
    }

    // ---- vectorized weight staging: 1024 uint4, 4 per thread ----
    {
        const uint4* src = reinterpret_cast<const uint4*>(g_wh);
        uint4* dst = reinterpret_cast<uint4*>(s_wh);
        dst[t]       = src[t];
        dst[t + 256] = src[t + 256];
        dst[t + 512] = src[t + 512];
        dst[t + 768] = src[t + 768];
    }
    if (t < 64) { s_b1[t] = b1[t]; s_db1[t] = db1[t]; }
    if (t < 32) { s_b2[t] = b2[t]; }
    __syncthreads();

    const __half* s_w1t  = s_wh;
    const __half* s_w2t  = s_wh + 2048;
    const __half* s_dw1t = s_wh + 4096;

    // ---- pack A1 ----
    uint32_t A1[2][2][4];
#pragma unroll
    for (int mt = 0; mt < 2; mt++)
#pragma unroll
        for (int ks = 0; ks < 2; ks++)
#pragma unroll
            for (int r = 0; r < 4; r++)
                A1[mt][ks][r] = f2_to_h2(zraw[mt][ks][r].x, zraw[mt][ks][r].y);

    // ---- GEMM1: C1 = z @ w1 + b1 ----
    float C1[2][8][4];
#pragma unroll
    for (int nt = 0; nt < 8; nt++) {
        float2 bb = *reinterpret_cast<const float2*>(&s_b1[nt * 8 + 2 * tig]);
#pragma unroll
        for (int mt = 0; mt < 2; mt++) {
            C1[mt][nt][0] = bb.x; C1[mt][nt][1] = bb.y;
            C1[mt][nt][2] = bb.x; C1[mt][nt][3] = bb.y;
        }
    }
#pragma unroll
    for (int nt = 0; nt < 8; nt++) {
#pragma unroll
        for (int ks = 0; ks < 2; ks++) {
            const __half* wp = &s_w1t[(nt * 8 + gid) * 32 + ks * 16 + 2 * tig];
            uint32_t b0 = *reinterpret_cast<const uint32_t*>(wp);
            uint32_t b1v = *reinterpret_cast<const uint32_t*>(wp + 8);
            mma16816(C1[0][nt], A1[0][ks], b0, b1v);
            mma16816(C1[1][nt], A1[1][ks], b0, b1v);
        }
    }

    // ---- relu + pack -> A2 ----
    uint32_t A2[2][4][4];
#pragma unroll
    for (int mt = 0; mt < 2; mt++)
#pragma unroll
        for (int kt = 0; kt < 4; kt++) {
            A2[mt][kt][0] = f2_to_h2_relu(C1[mt][2*kt][0],   C1[mt][2*kt][1]);
            A2[mt][kt][1] = f2_to_h2_relu(C1[mt][2*kt][2],   C1[mt][2*kt][3]);
            A2[mt][kt][2] = f2_to_h2_relu(C1[mt][2*kt+1][0], C1[mt][2*kt+1][1]);
            A2[mt][kt][3] = f2_to_h2_relu(C1[mt][2*kt+1][2], C1[mt][2*kt+1][3]);
        }

    // ---- GEMM2: C2 = h @ w2 + b2 ----
    float C2[2][4][4];
#pragma unroll
    for (int nt = 0; nt < 4; nt++) {
        float2 bb = *reinterpret_cast<const float2*>(&s_b2[nt * 8 + 2 * tig]);
#pragma unroll
        for (int mt = 0; mt < 2; mt++) {
            C2[mt][nt][0] = bb.x; C2[mt][nt][1] = bb.y;
            C2[mt][nt][2] = bb.x; C2[mt][nt][3] = bb.y;
        }
    }
#pragma unroll
    for (int nt = 0; nt < 4; nt++) {
#pragma unroll
        for (int ks = 0; ks < 4; ks++) {
            const __half* wp = &s_w2t[(nt * 8 + gid) * 64 + ks * 16 + 2 * tig];
            uint32_t b0 = *reinterpret_cast<const uint32_t*>(wp);
            uint32_t b1v = *reinterpret_cast<const uint32_t*>(wp + 8);
            mma16816(C2[0][nt], A2[0][ks], b0, b1v);
            mma16816(C2[1][nt], A2[1][ks], b0, b1v);
        }
    }

    // ---- pack zl -> A3 ----
    uint32_t A3[2][2][4];
#pragma unroll
    for (int mt = 0; mt < 2; mt++)
#pragma unroll
        for (int kt = 0; kt < 2; kt++) {
            A3[mt][kt][0] = f2_to_h2(C2[mt][2*kt][0],   C2[mt][2*kt][1]);
            A3[mt][kt][1] = f2_to_h2(C2[mt][2*kt][2],   C2[mt][2*kt][3]);
            A3[mt][kt][2] = f2_to_h2(C2[mt][2*kt+1][0], C2[mt][2*kt+1][1]);
            A3[mt][kt][3] = f2_to_h2(C2[mt][2*kt+1][2], C2[mt][2*kt+1][3]);
        }

    // ---- GEMM3 halves: hh=0 -> a (bias db1), hh=1 -> b ----
#pragma unroll
    for (int hh = 0; hh < 2; hh++) {
        float C3[2][8][4];
#pragma unroll
        for (int nt = 0; nt < 8; nt++) {
            float bx = 0.0f, by = 0.0f;
            if (hh == 0) {
                float2 bb = *reinterpret_cast<const float2*>(&s_db1[nt * 8 + 2 * tig]);
                bx = bb.x; by = bb.y;
            }
#pragma unroll
            for (int mt = 0; mt < 2; mt++) {
                C3[mt][nt][0] = bx; C3[mt][nt][1] = by;
                C3[mt][nt][2] = bx; C3[mt][nt][3] = by;
            }
        }
        const int koff = hh * 32;
#pragma unroll
        for (int nt = 0; nt < 8; nt++) {
#pragma unroll
            for (int ks = 0; ks < 2; ks++) {
                const __half* wp = &s_dw1t[(nt * 8 + gid) * 64 + koff + ks * 16 + 2 * tig];
                uint32_t b0 = *reinterpret_cast<const uint32_t*>(wp);
                uint32_t b1v = *reinterpret_cast<const uint32_t*>(wp + 8);
                mma16816(C3[0][nt], A3[0][ks], b0, b1v);
                mma16816(C3[1][nt], A3[1][ks], b0, b1v);
            }
        }

        __syncthreads();
#pragma unroll
        for (int mt = 0; mt < 2; mt++) {
            const int lr0 = wid * 32 + mt * 16 + gid;
            const int lr1 = lr0 + 8;
#pragma unroll
            for (int nt = 0; nt < 8; nt++) {
                *reinterpret_cast<uint32_t*>(&s_out[lr0 * 64 + nt * 8 + 2 * tig]) =
                    f2_to_h2(C3[mt][nt][0], C3[mt][nt][1]);
                *reinterpret_cast<uint32_t*>(&s_out[lr1 * 64 + nt * 8 + 2 * tig]) =
                    f2_to_h2(C3[mt][nt][2], C3[mt][nt][3]);
            }
        }
        __syncthreads();

        __half* dst = hh ? g_bh : g_ah;
        const int blk0 = blockIdx.x * 256;
#pragma unroll
        for (int it = 0; it < 8; it++) {
            int idx = it * 256 + t;
            int row = blk0 + (idx >> 3);
            if (row < n_nodes) {
                reinterpret_cast<uint4*>(dst)[(size_t)row * 8 + (idx & 7)] =
                    reinterpret_cast<const uint4*>(s_out)[idx];
            }
        }
    }
}

// ---------------------------------------------------------------------------
// Edge kernel (R6 configuration — stable 67.5us).
// ---------------------------------------------------------------------------
__device__ __forceinline__ float edge_dot(uint4 ua, uint4 ub,
                                          float4 w0, float4 w1)
{
    const __half2* pa = reinterpret_cast<const __half2*>(&ua);
    const __half2* pb = reinterpret_cast<const __half2*>(&ub);
    const __half2 zero2 = __float2half2_rn(0.0f);
    float2 f0 = __half22float2(__hmax2(__hadd2(pa[0], pb[0]), zero2));
    float2 f1 = __half22float2(__hmax2(__hadd2(pa[1], pb[1]), zero2));
    float2 f2 = __half22float2(__hmax2(__hadd2(pa[2], pb[2]), zero2));
    float2 f3 = __half22float2(__hmax2(__hadd2(pa[3], pb[3]), zero2));
    float acc;
    acc = f0.x * w0.x;
    acc = fmaf(f0.y, w0.y, acc);
    acc = fmaf(f1.x, w0.z, acc);
    acc = fmaf(f1.y, w0.w, acc);
    acc = fmaf(f2.x, w1.x, acc);
    acc = fmaf(f2.y, w1.y, acc);
    acc = fmaf(f3.x, w1.z, acc);
    acc = fmaf(f3.y, w1.w, acc);
    return acc;
}

__global__ void __launch_bounds__(256)
edge_kernel(const int* __restrict__ edge_index,  // [2, E] int32
            const float* __restrict__ dw2,       // [64]
            const float* __restrict__ db2,       // [1]
            float* __restrict__ out, int n_edges)
{
    const int lane = threadIdx.x & 31;
    const int s    = lane >> 3;
    const int q    = lane & 7;
    const int warp_g = (blockIdx.x * blockDim.x + threadIdx.x) >> 5;
    const int e0 = warp_g * 16 + s * 4;

    const float4 w0 = __ldg(reinterpret_cast<const float4*>(dw2) + 2 * q);
    const float4 w1 = __ldg(reinterpret_cast<const float4*>(dw2) + 2 * q + 1);
    const float bias = __ldg(db2);
    const uint4* Ab = reinterpret_cast<const uint4*>(g_ah);
    const uint4* Bb = reinterpret_cast<const uint4*>(g_bh);
    const unsigned mask = 0xFFu << (s * 8);

    if (e0 + 4 <= n_edges && (n_edges & 3) == 0) {
        const int4 iv = __ldg(reinterpret_cast<const int4*>(edge_index + e0));
        const int4 jv = __ldg(reinterpret_cast<const int4*>(edge_index + n_edges + e0));

        const uint4 ua0 = Ab[(size_t)iv.x * 8 + q];
        const uint4 ub0 = Bb[(size_t)jv.x * 8 + q];
        const uint4 ua1 = Ab[(size_t)iv.y * 8 + q];
        const uint4 ub1 = Bb[(size_t)jv.y * 8 + q];
        const uint4 ua2 = Ab[(size_t)iv.z * 8 + q];
        const uint4 ub2 = Bb[(size_t)jv.z * 8 + q];
        const uint4 ua3 = Ab[(size_t)iv.w * 8 + q];
        const uint4 ub3 = Bb[(size_t)jv.w * 8 + q];

        float r0 = edge_dot(ua0, ub0, w0, w1);
        float r1 = edge_dot(ua1, ub1, w0, w1);
        float r2 = edge_dot(ua2, ub2, w0, w1);
        float r3 = edge_dot(ua3, ub3, w0, w1);

        r0 += __shfl_xor_sync(mask, r0, 4);
        r1 += __shfl_xor_sync(mask, r1, 4);
        r2 += __shfl_xor_sync(mask, r2, 4);
        r3 += __shfl_xor_sync(mask, r3, 4);
        r0 += __shfl_xor_sync(mask, r0, 2);
        r1 += __shfl_xor_sync(mask, r1, 2);
        r2 += __shfl_xor_sync(mask, r2, 2);
        r3 += __shfl_xor_sync(mask, r3, 2);
        r0 += __shfl_xor_sync(mask, r0, 1);
        r1 += __shfl_xor_sync(mask, r1, 1);
        r2 += __shfl_xor_sync(mask, r2, 1);
        r3 += __shfl_xor_sync(mask, r3, 1);

        if (q == 0) {
            *reinterpret_cast<float4*>(out + e0) =
                make_float4(r0 + bias, r1 + bias, r2 + bias, r3 + bias);
        }
    } else {
#pragma unroll
        for (int t = 0; t < 4; t++) {
            const int e = e0 + t;
            const bool live = (e < n_edges);
            int i = 0, j = 0;
            if (live) {
                i = __ldg(edge_index + e);
                j = __ldg(edge_index + n_edges + e);
            }
            uint4 ua = make_uint4(0, 0, 0, 0), ub = make_uint4(0, 0, 0, 0);
            if (live) {
                ua = Ab[(size_t)i * 8 + q];
                ub = Bb[(size_t)j * 8 + q];
            }
            float acc = edge_dot(ua, ub, w0, w1);
            acc += __shfl_xor_sync(mask, acc, 4);
            acc += __shfl_xor_sync(mask, acc, 2);
            acc += __shfl_xor_sync(mask, acc, 1);
            if (live && q == 0) out[e] = acc + bias;
        }
    }
}

// ---------------------------------------------------------------------------
// Launch. Input order (metadata): z_mod, edge_index, w1, b1, w2, b2,
//                                 dw1, db1, dw2, db2
// ---------------------------------------------------------------------------
extern "C" void kernel_launch(void* const* d_in, const int* in_sizes, int n_in,
                              void* d_out, int out_size)
{
    const float* z_mod = (const float*)d_in[0];
    const int*   eidx  = (const int*)d_in[1];
    const float* w1    = (const float*)d_in[2];
    const float* b1    = (const float*)d_in[3];
    const float* w2    = (const float*)d_in[4];
    const float* b2    = (const float*)d_in[5];
    const float* dw1   = (const float*)d_in[6];
    const float* db1   = (const float*)d_in[7];
    const float* dw2   = (const float*)d_in[8];
    const float* db2   = (const float*)d_in[9];
    float* out = (float*)d_out;

    const int n_nodes = in_sizes[0] / 32;
    const int n_edges = in_sizes[1] / 2;

    prep_kernel<<<8, 256>>>(w1, w2, dw1);

    const int nb_node = (n_nodes + 255) / 256;
    node_kernel<<<nb_node, 256>>>(z_mod, b1, b2, db1, n_nodes);

    const int nb_edge = (n_edges + 127) / 128;
    edge_kernel<<<nb_edge, 256>>>(eidx, dw2, db2, out, n_edges);
}